// round 10
// baseline (speedup 1.0000x reference)
#include <cuda_runtime.h>
#include <cstdint>

// TransferNet: B=8192 sequences, T=1024 steps, C=6 channels.
// s_j(t) = a*feats[b,t,j] + (1-a)*ln( sum_i exp( s_i(t-1)*Tn[i][j] ) )
// s(0) = feats[b,0,:], out[b,t,:] = s(t).
//
// Thread-per-batch compute (all 6 channels + 6x6 softmaxed transitions in
// registers; zero shfl) with smem-staged coalesced I/O. R10: WARP-PRIVATE
// ownership — each warp copies and computes only its own 32 batches' rows,
// so there are NO block barriers at all, only __syncwarp(). Warps free-run
// and naturally desynchronize: one warp's global-load latency hides under
// another's MUFU burst. launch_bounds(64,7) lifts the reg cap to 146 (no
// spills; 1024 blocks still resident in one wave at 7 blocks/SM).
//
// T split into NCHUNK=8 chunks of 128 steps (the map is a contraction,
// per-step error factor ~0.2; W=8 warmup -> seed error ~1.3e-5 << 1e-3).

constexpr int T_STEPS  = 1024;
constexpr int C        = 6;
constexpr int BLOCK    = 64;            // 2 independent warps, 32 batches each
constexpr int TT       = 16;            // steps per tile
constexpr int NTILE    = 8;             // tiles per chunk
constexpr int CT       = TT * NTILE;    // 128 steps per chunk
constexpr int NCHUNK   = T_STEPS / CT;  // 8
constexpr int W        = 8;             // warmup steps (incl. seed), even
constexpr int ROW      = T_STEPS * C;   // 6144
constexpr int TILEF    = TT * C;        // 96 floats per (batch, tile)
constexpr int PITCH    = TILEF + 1;     // 97, odd -> conflict-free LDS/STS
constexpr float LOG2E_F = 1.4426950408889634f;
constexpr float LN2_F   = 0.6931471805599453f;

__device__ __forceinline__ float ex2f(float x) {
    float r; asm("ex2.approx.ftz.f32 %0, %1;" : "=f"(r) : "f"(x)); return r;
}
__device__ __forceinline__ float lg2f(float x) {
    float r; asm("lg2.approx.ftz.f32 %0, %1;" : "=f"(r) : "f"(x)); return r;
}

// One step, all 6 channels in-thread. t2[i*6+j] = Tn_softmax[i][j]*log2(e).
__device__ __forceinline__ void step6(float s[6], const float c[6],
                                      const float t2[36], float a, float c2) {
    float acc[6];
    #pragma unroll
    for (int j = 0; j < 6; ++j) {
        float e0 = ex2f(s[0] * t2[0 * 6 + j]);
        float e1 = ex2f(s[1] * t2[1 * 6 + j]);
        float e2 = ex2f(s[2] * t2[2 * 6 + j]);
        float e3 = ex2f(s[3] * t2[3 * 6 + j]);
        float e4 = ex2f(s[4] * t2[4 * 6 + j]);
        float e5 = ex2f(s[5] * t2[5 * 6 + j]);
        acc[j] = ((e0 + e1) + (e2 + e3)) + (e4 + e5);
    }
    #pragma unroll
    for (int j = 0; j < 6; ++j)
        s[j] = fmaf(a, c[j], c2 * lg2f(acc[j]));
}

__device__ __forceinline__ void load12(const float* p, float c[12]) {
    float4 v0 = *reinterpret_cast<const float4*>(p);
    float4 v1 = *reinterpret_cast<const float4*>(p + 4);
    float4 v2 = *reinterpret_cast<const float4*>(p + 8);
    c[0]=v0.x; c[1]=v0.y; c[2]=v0.z;  c[3]=v0.w;
    c[4]=v1.x; c[5]=v1.y; c[6]=v1.z;  c[7]=v1.w;
    c[8]=v2.x; c[9]=v2.y; c[10]=v2.z; c[11]=v2.w;
}

__global__ __launch_bounds__(BLOCK, 7)
void transfer_kernel(const float* __restrict__ feats,
                     const float* __restrict__ alpha,
                     const float* __restrict__ trans,
                     float* __restrict__ out, int B)
{
    __shared__ float sm[BLOCK * PITCH];   // 24832 B

    const int tid  = threadIdx.x;
    const int warp = tid >> 5;
    const int lane = tid & 31;
    const int b0   = blockIdx.x * BLOCK;
    const int wb   = b0 + warp * 32;          // this warp's first batch
    const int chunk = blockIdx.y;
    const int t0 = chunk * CT;

    // a = sigmoid(alpha)
    const float av = alpha[0];
    const float a  = 1.0f / (1.0f + __expf(-av));
    const float c2 = (1.0f - a) * LN2_F;

    // Full row-softmax of transitions, scaled by log2(e). 36 regs.
    float t2[36];
    #pragma unroll
    for (int i = 0; i < 6; ++i) {
        float row[6], m = -1e30f;
        #pragma unroll
        for (int k = 0; k < 6; ++k) { row[k] = trans[i * 6 + k]; m = fmaxf(m, row[k]); }
        float sum = 0.f;
        #pragma unroll
        for (int k = 0; k < 6; ++k) { row[k] = ex2f((row[k] - m) * LOG2E_F); sum += row[k]; }
        float inv = LOG2E_F / sum;
        #pragma unroll
        for (int k = 0; k < 6; ++k) t2[i * 6 + k] = row[k] * inv;
    }

    // Warp-private smem region: rows [32*warp, 32*warp+32)
    float* smw = sm + warp * 32 * PITCH;
    // This warp's global bases (tile-relative added later)
    const float* fwb = feats + (size_t)wb * ROW + (size_t)t0 * C;
    float*       owb = out   + (size_t)wb * ROW + (size_t)t0 * C;

    // Warp copies a pair of batches per p: 192 floats = 6 rounds of 32.
    //   r=0..2: batch 2p,   float off 32r+lane
    //   r=3..5: batch 2p+1, float off 32(r-3)+lane
    // Global: 32 consecutive floats -> one 128B line. Smem: bank=lane.
    const bool wfull = (wb + 31 < B);

    float s[6];

    // ---- initial load: tile 0 (issue LDGs before warmup so the latency
    //      overlaps the warmup compute) ----
    #pragma unroll
    for (int p = 0; p < 16; ++p) {
        const int bl = 2 * p;
        float* r0 = smw + bl * PITCH;
        const float* g0 = fwb + (size_t)bl * ROW;
        if (wfull || wb + bl + 1 < B) {
            r0[lane]              = g0[lane];
            r0[32 + lane]         = g0[32 + lane];
            r0[64 + lane]         = g0[64 + lane];
            r0[PITCH + lane]      = g0[ROW + lane];
            r0[PITCH + 32 + lane] = g0[ROW + 32 + lane];
            r0[PITCH + 64 + lane] = g0[ROW + 64 + lane];
        } else if (wb + bl < B) {
            r0[lane]      = g0[lane];
            r0[32 + lane] = g0[32 + lane];
            r0[64 + lane] = g0[64 + lane];
        }
    }

    // ---- warmup (chunks > 0): seed s = feats[t0-W], W-1 unstored steps ----
    if (chunk > 0) {
        int bb = b0 + tid; if (bb >= B) bb = B - 1;
        const float* wp = feats + (size_t)bb * ROW + (size_t)(t0 - W) * C;
        float cw[12];
        load12(wp, cw);
        #pragma unroll
        for (int j = 0; j < 6; ++j) s[j] = cw[j];
        step6(s, cw + 6, t2, a, c2);
        #pragma unroll
        for (int k = 1; k < W / 2; ++k) {
            load12(wp + k * 12, cw);
            step6(s, cw,     t2, a, c2);
            step6(s, cw + 6, t2, a, c2);
        }
    }
    __syncwarp();

    float* srow = sm + tid * PITCH;
    const bool own = (b0 + tid < B);

    #pragma unroll 1
    for (int k = 0; k < NTILE; ++k) {
        // ---- compute tile k in place (thread = batch, own row only) ----
        if (own) {
            int tstart = 0;
            if (chunk == 0 && k == 0) {
                #pragma unroll
                for (int j = 0; j < 6; ++j) s[j] = srow[j];
                tstart = 1;   // slot 0 already holds s(0)
            }
            #pragma unroll 4
            for (int tt = tstart; tt < TT; ++tt) {
                float c[6];
                #pragma unroll
                for (int j = 0; j < 6; ++j) c[j] = srow[tt * 6 + j];
                step6(s, c, t2, a, c2);
                #pragma unroll
                for (int j = 0; j < 6; ++j) srow[tt * 6 + j] = s[j];
            }
        }
        __syncwarp();

        // ---- fused: store tile k (LDS->STG) + load tile k+1 (LDG->STS).
        //      Per smem word, store-read precedes load-write in the SAME
        //      thread: program order guarantees correctness. ----
        float* gd = owb + (size_t)(k * TILEF);
        const float* gl = fwb + (size_t)((k + 1) * TILEF);
        const bool more = (k + 1 < NTILE);

        #pragma unroll
        for (int p = 0; p < 16; ++p) {
            const int bl = 2 * p;
            float* r0 = smw + bl * PITCH;
            float* g0 = gd + (size_t)bl * ROW;
            const float* gi = gl + (size_t)bl * ROW;
            if (wfull || wb + bl + 1 < B) {
                g0[lane]             = r0[lane];
                g0[32 + lane]        = r0[32 + lane];
                g0[64 + lane]        = r0[64 + lane];
                g0[ROW + lane]       = r0[PITCH + lane];
                g0[ROW + 32 + lane]  = r0[PITCH + 32 + lane];
                g0[ROW + 64 + lane]  = r0[PITCH + 64 + lane];
                if (more) {
                    r0[lane]              = gi[lane];
                    r0[32 + lane]         = gi[32 + lane];
                    r0[64 + lane]         = gi[64 + lane];
                    r0[PITCH + lane]      = gi[ROW + lane];
                    r0[PITCH + 32 + lane] = gi[ROW + 32 + lane];
                    r0[PITCH + 64 + lane] = gi[ROW + 64 + lane];
                }
            } else if (wb + bl < B) {
                g0[lane]      = r0[lane];
                g0[32 + lane] = r0[32 + lane];
                g0[64 + lane] = r0[64 + lane];
                if (more) {
                    r0[lane]      = gi[lane];
                    r0[32 + lane] = gi[32 + lane];
                    r0[64 + lane] = gi[64 + lane];
                }
            }
        }
        __syncwarp();
    }
}

extern "C" void kernel_launch(void* const* d_in, const int* in_sizes, int n_in,
                              void* d_out, int out_size) {
    const float* feats = (const float*)d_in[0];
    const float* alpha = (const float*)d_in[1];
    const float* trans = (const float*)d_in[2];
    float* out = (float*)d_out;
    (void)n_in; (void)out_size;

    int B = in_sizes[0] / (T_STEPS * C);
    dim3 grid((B + BLOCK - 1) / BLOCK, NCHUNK);
    transfer_kernel<<<grid, BLOCK>>>(feats, alpha, trans, out, B);
}

// round 11
// speedup vs baseline: 1.0732x; 1.0732x over previous
#include <cuda_runtime.h>
#include <cstdint>

// TransferNet: B=8192 sequences, T=1024 steps, C=6 channels.
// s_j(t) = a*feats[b,t,j] + (1-a)*ln( sum_i exp( s_i(t-1)*Tn[i][j] ) )
// s(0) = feats[b,0,:], out[b,t,:] = s(t).
//
// R9 base (best 117.5us): thread-per-batch compute (6 channels + 6x6
// softmaxed transitions in registers, zero shfl) + smem-staged coalesced
// I/O, NCHUNK=8 chunks of 128 steps, W=12 warmup (contraction ~0.2/step ->
// seed error ~5e-9), fused store+load phase, block barriers.
//
// R11 delta: PIPE SPLIT. MUFU was the binder (42 rt-8 ops/step = 336 cyc vs
// FMA 156). Move 9 of 36 exps to a deg-5 polynomial exp2 on the FMA pipe
// (floor/scale via ALU bit ops): MUFU 264 cyc vs FMA 264 cyc, balanced.
// Poly rel err ~1.7e-4 on 9/36 terms -> output err ~1.5e-5 << 1e-3.
// Also launch_bounds(64,7): reg cap 146 removes spills at the old 128 cap.

constexpr int T_STEPS  = 1024;
constexpr int C        = 6;
constexpr int BLOCK    = 64;            // threads = batches per block
constexpr int TT       = 16;            // steps per tile
constexpr int NTILE    = 8;             // tiles per chunk
constexpr int CT       = TT * NTILE;    // 128 steps per chunk
constexpr int NCHUNK   = T_STEPS / CT;  // 8
constexpr int W        = 12;            // warmup steps (incl. seed)
constexpr int ROW      = T_STEPS * C;   // 6144
constexpr int TILEF    = TT * C;        // 96 floats per (batch, tile)
constexpr int PITCH    = TILEF + 1;     // 97, odd -> conflict-free
constexpr float LOG2E_F = 1.4426950408889634f;
constexpr float LN2_F   = 0.6931471805599453f;

__device__ __forceinline__ float ex2f(float x) {
    float r; asm("ex2.approx.ftz.f32 %0, %1;" : "=f"(r) : "f"(x)); return r;
}
__device__ __forceinline__ float lg2f(float x) {
    float r; asm("lg2.approx.ftz.f32 %0, %1;" : "=f"(r) : "f"(x)); return r;
}

// Polynomial 2^x on the FMA/ALU pipes (MUFU-free). |x| <= ~80 safe.
// 2^x = 2^floor(x) * 2^f, f in [0,1); deg-5 Taylor of e^(f ln2),
// truncation rel err <= ~1.7e-4.
__device__ __forceinline__ float exp2poly(float x) {
    float xf = floorf(x);
    float f  = x - xf;
    float p  = fmaf(f, 0.0013333558f, 0.0096181291f);
    p = fmaf(f, p, 0.0555041087f);
    p = fmaf(f, p, 0.2402265070f);
    p = fmaf(f, p, 0.6931471806f);
    p = fmaf(f, p, 1.0f);
    int e = (int)xf;
    return __int_as_float(__float_as_int(p) + (e << 23));
}

// One step, all 6 channels in-thread. t2[i*6+j] = Tn_softmax[i][j]*log2(e).
// Pipe split: i=0 (all j) and i=1 (j<3) use exp2poly -> 9 of 36 exps on
// FMA pipe, 27 + 6 lg2 remain on MUFU. j is compile-time after unroll.
__device__ __forceinline__ void step6(float s[6], const float c[6],
                                      const float t2[36], float a, float c2) {
    float acc[6];
    #pragma unroll
    for (int j = 0; j < 6; ++j) {
        float e0 = exp2poly(s[0] * t2[0 * 6 + j]);
        float e1 = (j < 3) ? exp2poly(s[1] * t2[1 * 6 + j])
                           : ex2f(s[1] * t2[1 * 6 + j]);
        float e2 = ex2f(s[2] * t2[2 * 6 + j]);
        float e3 = ex2f(s[3] * t2[3 * 6 + j]);
        float e4 = ex2f(s[4] * t2[4 * 6 + j]);
        float e5 = ex2f(s[5] * t2[5 * 6 + j]);
        acc[j] = ((e0 + e1) + (e2 + e3)) + (e4 + e5);
    }
    #pragma unroll
    for (int j = 0; j < 6; ++j)
        s[j] = fmaf(a, c[j], c2 * lg2f(acc[j]));
}

__device__ __forceinline__ void load12(const float* p, float c[12]) {
    float4 v0 = *reinterpret_cast<const float4*>(p);
    float4 v1 = *reinterpret_cast<const float4*>(p + 4);
    float4 v2 = *reinterpret_cast<const float4*>(p + 8);
    c[0]=v0.x; c[1]=v0.y; c[2]=v0.z;  c[3]=v0.w;
    c[4]=v1.x; c[5]=v1.y; c[6]=v1.z;  c[7]=v1.w;
    c[8]=v2.x; c[9]=v2.y; c[10]=v2.z; c[11]=v2.w;
}

__global__ __launch_bounds__(BLOCK, 7)
void transfer_kernel(const float* __restrict__ feats,
                     const float* __restrict__ alpha,
                     const float* __restrict__ trans,
                     float* __restrict__ out, int B)
{
    __shared__ float sm[BLOCK * PITCH];   // 24832 B

    const int tid = threadIdx.x;
    const int b0  = blockIdx.x * BLOCK;
    const int chunk = blockIdx.y;
    const int t0 = chunk * CT;
    int nvalid = B - b0; if (nvalid > BLOCK) nvalid = BLOCK;

    // a = sigmoid(alpha)
    const float av = alpha[0];
    const float a  = 1.0f / (1.0f + __expf(-av));
    const float c2 = (1.0f - a) * LN2_F;

    // Full row-softmax of transitions, scaled by log2(e). 36 regs.
    float t2[36];
    #pragma unroll
    for (int i = 0; i < 6; ++i) {
        float row[6], m = -1e30f;
        #pragma unroll
        for (int k = 0; k < 6; ++k) { row[k] = trans[i * 6 + k]; m = fmaxf(m, row[k]); }
        float sum = 0.f;
        #pragma unroll
        for (int k = 0; k < 6; ++k) { row[k] = ex2f((row[k] - m) * LOG2E_F); sum += row[k]; }
        float inv = LOG2E_F / sum;
        #pragma unroll
        for (int k = 0; k < 6; ++k) t2[i * 6 + k] = row[k] * inv;
    }

    // Copy-round constant offsets: per pair of batches, 192 = 3*64 floats.
    //  round0: r=tid        -> batch 0 of pair, idx tid
    //  round1: r=tid+64     -> tid<32: batch0 idx tid+64 ; else batch1 idx tid-32
    //  round2: r=tid+128    -> batch1, idx tid+32
    // Branch is warp-uniform (warp0: tid<32, warp1: tid>=32).
    const bool loh = (tid < 32);
    const int  s1  = loh ? (64 + tid) : (PITCH + tid - 32);
    const int  g1  = loh ? (64 + tid) : (ROW + tid - 32);
    const int  s2  = PITCH + 32 + tid;
    const long g2  = (long)ROW + 32 + tid;

    const bool full = (nvalid == BLOCK);

    const float* fbase = feats + (size_t)b0 * ROW + (size_t)t0 * C;
    float*       obase = out   + (size_t)b0 * ROW + (size_t)t0 * C;

    float s[6];

    // ---- warmup (chunks > 0): seed s = feats[t0-W], 11 unstored steps ----
    if (chunk > 0) {
        int bb = b0 + tid; if (bb >= B) bb = B - 1;
        const float* wp = feats + (size_t)bb * ROW + (size_t)(t0 - W) * C;
        float cw[12];
        load12(wp, cw);
        #pragma unroll
        for (int j = 0; j < 6; ++j) s[j] = cw[j];
        step6(s, cw + 6, t2, a, c2);
        #pragma unroll
        for (int k = 1; k < W / 2; ++k) {
            load12(wp + k * 12, cw);
            step6(s, cw,     t2, a, c2);
            step6(s, cw + 6, t2, a, c2);
        }
    }

    // ---- initial load: tile 0 ----
    if (full) {
        #pragma unroll
        for (int p = 0; p < BLOCK / 2; ++p) {
            const float* g0 = fbase + (size_t)(2 * p) * ROW;
            float* sp = sm + 2 * p * PITCH;
            sp[tid] = g0[tid];
            sp[s1]  = g0[g1];
            sp[s2]  = g0[g2];
        }
    } else {
        #pragma unroll 1
        for (int p = 0; p < BLOCK / 2; ++p) {
            int bl = 2 * p;
            const float* g0 = fbase + (size_t)bl * ROW;
            float* sp = sm + bl * PITCH;
            if (bl + 1 < nvalid) { sp[tid] = g0[tid]; sp[s1] = g0[g1]; sp[s2] = g0[g2]; }
            else if (bl < nvalid) { sp[tid] = g0[tid]; if (loh) sp[s1] = g0[g1]; }
        }
    }

    float* srow = sm + tid * PITCH;
    const bool own = (b0 + tid < B);

    #pragma unroll 1
    for (int k = 0; k < NTILE; ++k) {
        __syncthreads();

        // ---- compute tile k in place (thread = batch, scalar LDS/STS) ----
        if (own) {
            int tstart = 0;
            if (chunk == 0 && k == 0) {
                #pragma unroll
                for (int j = 0; j < 6; ++j) s[j] = srow[j];
                tstart = 1;   // slot 0 already holds s(0)
            }
            #pragma unroll 4
            for (int tt = tstart; tt < TT; ++tt) {
                float c[6];
                #pragma unroll
                for (int j = 0; j < 6; ++j) c[j] = srow[tt * 6 + j];
                step6(s, c, t2, a, c2);
                #pragma unroll
                for (int j = 0; j < 6; ++j) srow[tt * 6 + j] = s[j];
            }
        }
        __syncthreads();

        // ---- fused: store tile k (LDS->STG) + load tile k+1 (LDG->STS).
        //      Same thread owns both accesses to each smem word: program
        //      order guarantees the read-before-write. ----
        float* gd = obase + (size_t)(k * TILEF);
        const float* gl = fbase + (size_t)((k + 1) * TILEF);
        const bool more = (k + 1 < NTILE);

        if (full) {
            #pragma unroll
            for (int p = 0; p < BLOCK / 2; ++p) {
                float* g0 = gd + (size_t)(2 * p) * ROW;
                float* sp = sm + 2 * p * PITCH;
                g0[tid] = sp[tid];
                g0[g1]  = sp[s1];
                g0[g2]  = sp[s2];
                if (more) {
                    const float* gi = gl + (size_t)(2 * p) * ROW;
                    sp[tid] = gi[tid];
                    sp[s1]  = gi[g1];
                    sp[s2]  = gi[g2];
                }
            }
        } else {
            #pragma unroll 1
            for (int p = 0; p < BLOCK / 2; ++p) {
                int bl = 2 * p;
                float* g0 = gd + (size_t)bl * ROW;
                float* sp = sm + bl * PITCH;
                if (bl + 1 < nvalid) {
                    g0[tid] = sp[tid]; g0[g1] = sp[s1]; g0[g2] = sp[s2];
                    if (more) {
                        const float* gi = gl + (size_t)bl * ROW;
                        sp[tid] = gi[tid]; sp[s1] = gi[g1]; sp[s2] = gi[g2];
                    }
                } else if (bl < nvalid) {
                    g0[tid] = sp[tid]; if (loh) g0[g1] = sp[s1];
                    if (more) {
                        const float* gi = gl + (size_t)bl * ROW;
                        sp[tid] = gi[tid]; if (loh) sp[s1] = gi[g1];
                    }
                }
            }
        }
    }
}

extern "C" void kernel_launch(void* const* d_in, const int* in_sizes, int n_in,
                              void* d_out, int out_size) {
    const float* feats = (const float*)d_in[0];
    const float* alpha = (const float*)d_in[1];
    const float* trans = (const float*)d_in[2];
    float* out = (float*)d_out;
    (void)n_in; (void)out_size;

    int B = in_sizes[0] / (T_STEPS * C);
    dim3 grid((B + BLOCK - 1) / BLOCK, NCHUNK);
    transfer_kernel<<<grid, BLOCK>>>(feats, alpha, trans, out, B);
}

// round 12
// speedup vs baseline: 1.1519x; 1.0733x over previous
#include <cuda_runtime.h>
#include <cstdint>

// TransferNet: B=8192 sequences, T=1024 steps, C=6 channels.
// s_j(t) = a*feats[b,t,j] + (1-a)*ln( sum_i exp( s_i(t-1)*Tn[i][j] ) )
// s(0) = feats[b,0,:], out[b,t,:] = s(t).
//
// R9 skeleton (best 117.5us): thread-per-batch compute (6 channels + 6x6
// softmaxed transitions in registers; zero shfl) + smem-staged coalesced
// I/O; T split into NCHUNK=8 chunks of 128 steps (contraction ~0.2/step,
// W=8 warmup -> seed error ~6e-8, measured in R10).
//
// R12 delta: cp.async DOUBLE BUFFER. Compute phase leaves MIO idle in this
// mapping, so tile k+2 is prefetched with cp.async during compute/store of
// k+1 and its DRAM latency disappears from the critical path (in R9 every
// tile boundary exposed a full load latency inside barrier lockstep).
// TT=8, PITCH=49 (odd -> conflict-free LDS), two 12.5KB buffers.
// Copy mapping: batch-QUADS, 4*48=192 floats = 3 rounds of 64 threads,
// per-thread constant offsets, warp-coalesced.

constexpr int T_STEPS  = 1024;
constexpr int C        = 6;
constexpr int BLOCK    = 64;            // threads = batches per block
constexpr int TT       = 8;             // steps per tile
constexpr int NTILE    = 16;            // tiles per chunk
constexpr int CT       = TT * NTILE;    // 128 steps per chunk
constexpr int NCHUNK   = T_STEPS / CT;  // 8
constexpr int W        = 8;             // warmup steps (incl. seed), even
constexpr int ROW      = T_STEPS * C;   // 6144
constexpr int TILEF    = TT * C;        // 48 floats per (batch, tile)
constexpr int PITCH    = TILEF + 1;     // 49, odd -> conflict-free
constexpr int NQ       = BLOCK / 4;     // 16 batch-quads
constexpr float LOG2E_F = 1.4426950408889634f;
constexpr float LN2_F   = 0.6931471805599453f;

__device__ __forceinline__ float ex2f(float x) {
    float r; asm("ex2.approx.ftz.f32 %0, %1;" : "=f"(r) : "f"(x)); return r;
}
__device__ __forceinline__ float lg2f(float x) {
    float r; asm("lg2.approx.ftz.f32 %0, %1;" : "=f"(r) : "f"(x)); return r;
}
__device__ __forceinline__ void cp4(unsigned int saddr, const float* gptr) {
    asm volatile("cp.async.ca.shared.global [%0], [%1], 4;\n"
                 :: "r"(saddr), "l"(gptr) : "memory");
}
__device__ __forceinline__ void cp_commit() {
    asm volatile("cp.async.commit_group;\n" ::: "memory");
}
template <int N>
__device__ __forceinline__ void cp_wait() {
    asm volatile("cp.async.wait_group %0;\n" :: "n"(N) : "memory");
}

// One step, all 6 channels in-thread. t2[i*6+j] = Tn_softmax[i][j]*log2(e).
__device__ __forceinline__ void step6(float s[6], const float c[6],
                                      const float t2[36], float a, float c2) {
    float acc[6];
    #pragma unroll
    for (int j = 0; j < 6; ++j) {
        float e0 = ex2f(s[0] * t2[0 * 6 + j]);
        float e1 = ex2f(s[1] * t2[1 * 6 + j]);
        float e2 = ex2f(s[2] * t2[2 * 6 + j]);
        float e3 = ex2f(s[3] * t2[3 * 6 + j]);
        float e4 = ex2f(s[4] * t2[4 * 6 + j]);
        float e5 = ex2f(s[5] * t2[5 * 6 + j]);
        acc[j] = ((e0 + e1) + (e2 + e3)) + (e4 + e5);
    }
    #pragma unroll
    for (int j = 0; j < 6; ++j)
        s[j] = fmaf(a, c[j], c2 * lg2f(acc[j]));
}

__device__ __forceinline__ void load12(const float* p, float c[12]) {
    float4 v0 = *reinterpret_cast<const float4*>(p);
    float4 v1 = *reinterpret_cast<const float4*>(p + 4);
    float4 v2 = *reinterpret_cast<const float4*>(p + 8);
    c[0]=v0.x; c[1]=v0.y; c[2]=v0.z;  c[3]=v0.w;
    c[4]=v1.x; c[5]=v1.y; c[6]=v1.z;  c[7]=v1.w;
    c[8]=v2.x; c[9]=v2.y; c[10]=v2.z; c[11]=v2.w;
}

__global__ __launch_bounds__(BLOCK, 7)
void transfer_kernel(const float* __restrict__ feats,
                     const float* __restrict__ alpha,
                     const float* __restrict__ trans,
                     float* __restrict__ out, int B)
{
    __shared__ float sm[2][BLOCK * PITCH];   // 2 x 12544 B

    const int tid = threadIdx.x;
    const int b0  = blockIdx.x * BLOCK;
    const int chunk = blockIdx.y;
    const int t0 = chunk * CT;
    int nvalid = B - b0; if (nvalid > BLOCK) nvalid = BLOCK;
    const bool full = (nvalid == BLOCK);

    // Per-round copy constants: quad = 4 batches, 192 floats = 3 rounds.
    // round r: idx = tid + 64r -> batch-in-quad bq = idx/48, off = idx%48.
    int soff[3], goff[3], bqr[3];
    #pragma unroll
    for (int r = 0; r < 3; ++r) {
        int idx = tid + 64 * r;
        int bq  = idx / 48;
        int off = idx - 48 * bq;
        soff[r] = bq * PITCH + off;
        goff[r] = bq * ROW + off;
        bqr[r]  = bq;
    }

    const float* fbase = feats + (size_t)b0 * ROW + (size_t)t0 * C;
    float*       obase = out   + (size_t)b0 * ROW + (size_t)t0 * C;

    // ---- prologue: async prefetch tiles 0 and 1 (overlaps setup+warmup) ----
    #pragma unroll
    for (int kk = 0; kk < 2; ++kk) {
        #pragma unroll
        for (int q = 0; q < NQ; ++q) {
            unsigned sb = (unsigned)__cvta_generic_to_shared(&sm[kk][4 * q * PITCH]);
            const float* gq = fbase + (size_t)(4 * q) * ROW + kk * TILEF;
            #pragma unroll
            for (int r = 0; r < 3; ++r) {
                const float* gp = gq + goff[r];
                if (!full && (4 * q + bqr[r]) >= nvalid) gp = fbase;  // clamp
                cp4(sb + (unsigned)(soff[r] * 4), gp);
            }
        }
        cp_commit();
    }

    // a = sigmoid(alpha)
    const float av = alpha[0];
    const float a  = 1.0f / (1.0f + __expf(-av));
    const float c2 = (1.0f - a) * LN2_F;

    // Full row-softmax of transitions, scaled by log2(e). 36 regs.
    float t2[36];
    #pragma unroll
    for (int i = 0; i < 6; ++i) {
        float row[6], m = -1e30f;
        #pragma unroll
        for (int k = 0; k < 6; ++k) { row[k] = trans[i * 6 + k]; m = fmaxf(m, row[k]); }
        float sum = 0.f;
        #pragma unroll
        for (int k = 0; k < 6; ++k) { row[k] = ex2f((row[k] - m) * LOG2E_F); sum += row[k]; }
        float inv = LOG2E_F / sum;
        #pragma unroll
        for (int k = 0; k < 6; ++k) t2[i * 6 + k] = row[k] * inv;
    }

    float s[6];

    // ---- warmup (chunks > 0): seed s = feats[t0-W], W-1 unstored steps ----
    if (chunk > 0) {
        int bb = b0 + tid; if (bb >= B) bb = B - 1;
        const float* wp = feats + (size_t)bb * ROW + (size_t)(t0 - W) * C;
        float cw[12];
        load12(wp, cw);
        #pragma unroll
        for (int j = 0; j < 6; ++j) s[j] = cw[j];
        step6(s, cw + 6, t2, a, c2);
        #pragma unroll
        for (int k = 1; k < W / 2; ++k) {
            load12(wp + k * 12, cw);
            step6(s, cw,     t2, a, c2);
            step6(s, cw + 6, t2, a, c2);
        }
    }

    const bool own = (b0 + tid < B);

    #pragma unroll 1
    for (int k = 0; k < NTILE; ++k) {
        float* buf = (k & 1) ? &sm[1][0] : &sm[0][0];
        cp_wait<1>();          // tile k resident (k+1 may still be in flight)
        __syncthreads();

        // ---- compute tile k in place (thread = batch, own row only) ----
        if (own) {
            float* srow = buf + tid * PITCH;
            if (chunk == 0 && k == 0) {
                #pragma unroll
                for (int j = 0; j < 6; ++j) s[j] = srow[j];   // s(0) = feats
                #pragma unroll
                for (int tt = 1; tt < TT; ++tt) {
                    float c[6];
                    #pragma unroll
                    for (int j = 0; j < 6; ++j) c[j] = srow[tt * 6 + j];
                    step6(s, c, t2, a, c2);
                    #pragma unroll
                    for (int j = 0; j < 6; ++j) srow[tt * 6 + j] = s[j];
                }
            } else {
                #pragma unroll
                for (int tt = 0; tt < TT; ++tt) {
                    float c[6];
                    #pragma unroll
                    for (int j = 0; j < 6; ++j) c[j] = srow[tt * 6 + j];
                    step6(s, c, t2, a, c2);
                    #pragma unroll
                    for (int j = 0; j < 6; ++j) srow[tt * 6 + j] = s[j];
                }
            }
        }
        __syncthreads();

        // ---- store tile k (LDS -> STG, coalesced by quads) ----
        float* gd = obase + (size_t)(k * TILEF);
        if (full) {
            #pragma unroll
            for (int q = 0; q < NQ; ++q) {
                const float* sp = buf + 4 * q * PITCH;
                float* gq = gd + (size_t)(4 * q) * ROW;
                #pragma unroll
                for (int r = 0; r < 3; ++r) gq[goff[r]] = sp[soff[r]];
            }
        } else {
            #pragma unroll 1
            for (int q = 0; q < NQ; ++q) {
                const float* sp = buf + 4 * q * PITCH;
                float* gq = gd + (size_t)(4 * q) * ROW;
                #pragma unroll
                for (int r = 0; r < 3; ++r)
                    if (4 * q + bqr[r] < nvalid) gq[goff[r]] = sp[soff[r]];
            }
        }
        __syncthreads();   // all LDS of buf retired before cp.async overwrites

        // ---- prefetch tile k+2 into buf ----
        if (k + 2 < NTILE) {
            const float* gl = fbase + (size_t)((k + 2) * TILEF);
            #pragma unroll
            for (int q = 0; q < NQ; ++q) {
                unsigned sb = (unsigned)__cvta_generic_to_shared(buf + 4 * q * PITCH);
                const float* gq = gl + (size_t)(4 * q) * ROW;
                #pragma unroll
                for (int r = 0; r < 3; ++r) {
                    const float* gp = gq + goff[r];
                    if (!full && (4 * q + bqr[r]) >= nvalid) gp = fbase;
                    cp4(sb + (unsigned)(soff[r] * 4), gp);
                }
            }
        }
        cp_commit();       // commit every iteration to keep group count aligned
    }
}

extern "C" void kernel_launch(void* const* d_in, const int* in_sizes, int n_in,
                              void* d_out, int out_size) {
    const float* feats = (const float*)d_in[0];
    const float* alpha = (const float*)d_in[1];
    const float* trans = (const float*)d_in[2];
    float* out = (float*)d_out;
    (void)n_in; (void)out_size;

    int B = in_sizes[0] / (T_STEPS * C);
    dim3 grid((B + BLOCK - 1) / BLOCK, NCHUNK);
    transfer_kernel<<<grid, BLOCK>>>(feats, alpha, trans, out, B);
}